// round 13
// baseline (speedup 1.0000x reference)
#include <cuda_runtime.h>

// Problem constants
#define VOCAB 50257
#define EMB   128
#define MEM   256   // memory slots (M)
#define BATCH 16    // batch (B)
#define SENT  64    // sentence length (S)
#define TBL   ((size_t)VOCAB * EMB)
#define FULLMASK 0xffffffffu

// Static scratch:
//  g_E[t][b][m][d] for t=0,1 only (E2 never materialized)   (4.2 MB)
//  g_u1[b]   : hop-0 state
//  g_prob[b] : hop-2 attention weights
//  g_flag[b] : release flag: hop block b finished (out=u2, prob2 ready)
__device__ __align__(16) float g_E[2][BATCH][MEM][EMB];
__device__ __align__(16) float g_u1[BATCH][EMB];
__device__ __align__(16) float g_prob[BATCH][MEM];
__device__ int g_flag[BATCH];

// ---------------------------------------------------------------------------
// Core gather-sum for one (t,b,m) unit with one warp: returns this lane's
// float4 slice of E_t[b][m]. 64 token rows x 512B coalesced LDG.128 —
// the structure measured at the LTS cap.
// ---------------------------------------------------------------------------
__device__ __forceinline__ float4 gather_core(const int* __restrict__ story,
                                              const float* __restrict__ C,
                                              int t, int b, int m, int lane) {
    const int* toks = story + ((size_t)m * BATCH + b) * SENT;
    const int tok_lo = toks[lane];
    const int tok_hi = toks[lane + 32];

    const float4* __restrict__ tab =
        (const float4*)(C + (size_t)(t + 1) * TBL);

    float4 a0 = make_float4(0.f, 0.f, 0.f, 0.f);
    float4 a1 = make_float4(0.f, 0.f, 0.f, 0.f);

#pragma unroll
    for (int s = 0; s < 32; s++) {
        int tok = __shfl_sync(FULLMASK, tok_lo, s);
        float4 v = __ldg(tab + (size_t)tok * (EMB / 4) + lane);
        a0.x += v.x; a0.y += v.y; a0.z += v.z; a0.w += v.w;
    }
#pragma unroll
    for (int s = 0; s < 32; s++) {
        int tok = __shfl_sync(FULLMASK, tok_hi, s);
        float4 v = __ldg(tab + (size_t)tok * (EMB / 4) + lane);
        a1.x += v.x; a1.y += v.y; a1.z += v.z; a1.w += v.w;
    }

    return make_float4(a0.x + a1.x, a0.y + a1.y, a0.z + a1.z, a0.w + a1.w);
}

__device__ __forceinline__ void gather_store(const int* __restrict__ story,
                                             const float* __restrict__ C,
                                             int t, int b, int m, int lane) {
    float4 acc = gather_core(story, C, t, b, m, lane);
    ((float4*)g_E[t][b][m])[lane] = acc;
}

// ---------------------------------------------------------------------------
// hop0 for batch b, 256 threads: g_u1[b] = mean_m E0[b][m]
// (hop-0 softmax of zero logits is exactly uniform -> plain mean; C0 unused)
// ---------------------------------------------------------------------------
__device__ __forceinline__ void hop0_256(int b) {
    __shared__ float4 wp0[8][32];
    const int tid = threadIdx.x, w = tid >> 5, lane = tid & 31;
    const float4* __restrict__ E0 = (const float4*)g_E[0][b];

    float4 acc = make_float4(0.f, 0.f, 0.f, 0.f);
#pragma unroll 4
    for (int k = 0; k < 32; k++) {
        float4 v = E0[(size_t)(w * 32 + k) * 32 + lane];
        acc.x += v.x; acc.y += v.y; acc.z += v.z; acc.w += v.w;
    }
    wp0[w][lane] = acc;
    __syncthreads();
    if (tid < 32) {
        float4 a = wp0[0][tid];
#pragma unroll
        for (int i = 1; i < 8; i++) {
            float4 c = wp0[i][tid];
            a.x += c.x; a.y += c.y; a.z += c.z; a.w += c.w;
        }
        a.x *= (1.f / MEM); a.y *= (1.f / MEM); a.z *= (1.f / MEM); a.w *= (1.f / MEM);
        ((float4*)g_u1[b])[tid] = a;
    }
}

// ---------------------------------------------------------------------------
// logits + softmax: prob[m] = softmax_m( Ep[m] . us )  (256 threads)
// ---------------------------------------------------------------------------
__device__ __forceinline__ void logits_softmax(const float4* __restrict__ Ep,
                                               const float4* us,
                                               float* prob, float* red) {
    const int tid = threadIdx.x, w = tid >> 5, lane = tid & 31;
    const int q = lane & 3, sl = lane >> 2;
#pragma unroll
    for (int pass = 0; pass < 4; pass++) {
        const int m = pass * 64 + w * 8 + sl;
        float pd = 0.f;
#pragma unroll
        for (int j = 0; j < 8; j++) {
            float4 e  = Ep[(size_t)m * 32 + q + 4 * j];
            float4 uu = us[q + 4 * j];
            pd += e.x * uu.x + e.y * uu.y + e.z * uu.z + e.w * uu.w;
        }
        pd += __shfl_xor_sync(FULLMASK, pd, 1);
        pd += __shfl_xor_sync(FULLMASK, pd, 2);
        if (q == 0) prob[m] = pd;
    }
    __syncthreads();

    float x = prob[tid];
    float mx = x;
#pragma unroll
    for (int off = 16; off; off >>= 1)
        mx = fmaxf(mx, __shfl_xor_sync(FULLMASK, mx, off));
    if (lane == 0) red[w] = mx;
    __syncthreads();
    mx = red[0];
#pragma unroll
    for (int i = 1; i < 8; i++) mx = fmaxf(mx, red[i]);
    __syncthreads();

    float ev = __expf(x - mx);
    float sv = ev;
#pragma unroll
    for (int off = 16; off; off >>= 1)
        sv += __shfl_xor_sync(FULLMASK, sv, off);
    if (lane == 0) red[w] = sv;
    __syncthreads();
    float tot = red[0];
#pragma unroll
    for (int i = 1; i < 8; i++) tot += red[i];

    prob[tid] = ev / tot;
    __syncthreads();
}

// ---------------------------------------------------------------------------
// K1: gather t0 (512 blocks x 8 warps). Block 0 also clears the flags.
// ---------------------------------------------------------------------------
__global__ void __launch_bounds__(256) k1_kernel(const int* __restrict__ story,
                                                 const float* __restrict__ C) {
    if (blockIdx.x == 0 && threadIdx.x < BATCH) g_flag[threadIdx.x] = 0;
    const int w = blockIdx.x * 8 + (threadIdx.x >> 5);
    gather_store(story, C, 0, w / MEM, w % MEM, threadIdx.x & 31);
}

// ---------------------------------------------------------------------------
// K2: hop0 (blocks 0..15) || gather t1 (blocks 16..527)
// ---------------------------------------------------------------------------
__global__ void __launch_bounds__(256) k2_kernel(const int* __restrict__ story,
                                                 const float* __restrict__ C) {
    if (blockIdx.x < 16) {
        hop0_256(blockIdx.x);
    } else {
        const int w = (blockIdx.x - 16) * 8 + (threadIdx.x >> 5);
        gather_store(story, C, 1, w / MEM, w % MEM, threadIdx.x & 31);
    }
}

// ---------------------------------------------------------------------------
// K3: blocks 0..15  : hop1 (u2 = u1 + attn(E0;E1)), write out[b] = u2, then
//                     prob2 = softmax(E1 . u2) -> g_prob[b]; release flag[b].
//     blocks 16..527: gather E2[b][m] into registers, wait for flag[b], then
//                     out[b] += prob2[b][m] * E2row  (atomic; E2 never stored).
// All 528 blocks are co-resident (<=4 blocks/SM needed, 592 slots) and the
// hop blocks are dispatched first, so the wait cannot deadlock.
// ---------------------------------------------------------------------------
__global__ void __launch_bounds__(256) k3_kernel(const int* __restrict__ story,
                                                 const float* __restrict__ C,
                                                 float* __restrict__ out) {
    if (blockIdx.x >= 16) {
        const int w    = (blockIdx.x - 16) * 8 + (threadIdx.x >> 5);
        const int b    = w / MEM, m = w % MEM;
        const int lane = threadIdx.x & 31;

        float4 acc = gather_core(story, C, 2, b, m, lane);   // E2[b][m] slice

        // acquire: hop block b has published out[b]=u2 and g_prob[b]
        if (lane == 0) {
            while (atomicAdd(&g_flag[b], 0) == 0) __nanosleep(128);
        }
        __syncwarp();
        __threadfence();

        const float p = g_prob[b][m];
        float* dst = out + (size_t)b * EMB + lane * 4;
        atomicAdd(dst + 0, p * acc.x);
        atomicAdd(dst + 1, p * acc.y);
        atomicAdd(dst + 2, p * acc.z);
        atomicAdd(dst + 3, p * acc.w);
        return;
    }

    __shared__ float4 us[32];
    __shared__ float4 us2[32];
    __shared__ float  prob[MEM];
    __shared__ float4 wp[8][32];
    __shared__ float  red[8];

    const int b = blockIdx.x, tid = threadIdx.x, w = tid >> 5, lane = tid & 31;
    const float4* __restrict__ E0 = (const float4*)g_E[0][b];
    const float4* __restrict__ E1 = (const float4*)g_E[1][b];

    if (tid < 32) us[tid] = ((const float4*)g_u1[b])[tid];
    __syncthreads();

    // hop1 attention: prob1 = softmax(E0 . u1)
    logits_softmax(E0, us, prob, red);

    // o1 = sum_m prob1[m] * E1[b][m]; u2 = u1 + o1; out[b] = u2
    {
        float4 acc = make_float4(0.f, 0.f, 0.f, 0.f);
#pragma unroll 4
        for (int k = 0; k < 32; k++) {
            const int mm = w * 32 + k;
            float p = prob[mm];
            float4 v = E1[(size_t)mm * 32 + lane];
            acc.x += p * v.x; acc.y += p * v.y; acc.z += p * v.z; acc.w += p * v.w;
        }
        wp[w][lane] = acc;
        __syncthreads();
        if (tid < 32) {
            float4 a = wp[0][tid];
#pragma unroll
            for (int i = 1; i < 8; i++) {
                float4 c = wp[i][tid];
                a.x += c.x; a.y += c.y; a.z += c.z; a.w += c.w;
            }
            float4 uu = us[tid];
            a.x += uu.x; a.y += uu.y; a.z += uu.z; a.w += uu.w;
            us2[tid] = a;
            ((float4*)out)[(size_t)b * 32 + tid] = a;   // gather warps add o2
        }
        __syncthreads();
    }

    // logits2: prob2 = softmax(E1 . u2) -> g_prob[b]
    logits_softmax(E1, us2, prob, red);
    g_prob[b][tid] = prob[tid];
    __syncthreads();

    // release
    if (tid == 0) {
        __threadfence();
        atomicExch(&g_flag[b], 1);
    }
}

extern "C" void kernel_launch(void* const* d_in, const int* in_sizes, int n_in,
                              void* d_out, int out_size) {
    const int*   story = (const int*)d_in[0];   // (256, 16, 64) int32
    const float* C     = (const float*)d_in[1]; // (4, 50257, 128) fp32
    float*       out   = (float*)d_out;         // (16, 128) fp32

    (void)in_sizes; (void)n_in; (void)out_size;

    k1_kernel<<<512, 256>>>(story, C);          // gather t0 (+ flag clear)
    k2_kernel<<<528, 256>>>(story, C);          // hop0 || gather t1
    k3_kernel<<<528, 256>>>(story, C, out);     // hop1+logits2 || gather t2 -> out
}

// round 14
// speedup vs baseline: 1.7986x; 1.7986x over previous
#include <cuda_runtime.h>

// Problem constants
#define VOCAB 50257
#define EMB   128
#define MEM   256   // memory slots (M)
#define BATCH 16    // batch (B)
#define SENT  64    // sentence length (S)
#define TBL   ((size_t)VOCAB * EMB)
#define FULLMASK 0xffffffffu

// Static scratch:
//  g_E[t][b][m][d] = sum_s C[t+1][story[m][b][s]][d]   (6.3 MB, t=0..2)
//  g_prob[b][m]    = hop-2 attention weights
__device__ __align__(16) float g_E[3][BATCH][MEM][EMB];
__device__ __align__(16) float g_prob[BATCH][MEM];

// ---------------------------------------------------------------------------
// Gather-sum one (t,b,m) unit with one warp from the fp32 table.
// 64 token rows x 512B coalesced LDG.128 — measured at ~90% of the LTS cap.
// ---------------------------------------------------------------------------
__device__ __forceinline__ void gather_unit(const int* __restrict__ story,
                                            const float* __restrict__ C,
                                            int t, int b, int m, int lane) {
    const int* toks = story + ((size_t)m * BATCH + b) * SENT;
    const int tok_lo = toks[lane];
    const int tok_hi = toks[lane + 32];

    const float4* __restrict__ tab =
        (const float4*)(C + (size_t)(t + 1) * TBL);

    float4 a0 = make_float4(0.f, 0.f, 0.f, 0.f);
    float4 a1 = make_float4(0.f, 0.f, 0.f, 0.f);

#pragma unroll
    for (int s = 0; s < 32; s++) {
        int tok = __shfl_sync(FULLMASK, tok_lo, s);
        float4 v = __ldg(tab + (size_t)tok * (EMB / 4) + lane);
        a0.x += v.x; a0.y += v.y; a0.z += v.z; a0.w += v.w;
    }
#pragma unroll
    for (int s = 0; s < 32; s++) {
        int tok = __shfl_sync(FULLMASK, tok_hi, s);
        float4 v = __ldg(tab + (size_t)tok * (EMB / 4) + lane);
        a1.x += v.x; a1.y += v.y; a1.z += v.z; a1.w += v.w;
    }

    float4 acc = make_float4(a0.x + a1.x, a0.y + a1.y, a0.z + a1.z, a0.w + a1.w);
    ((float4*)g_E[t][b][m])[lane] = acc;
}

// ---------------------------------------------------------------------------
// logits + softmax: prob[m] = softmax_m( Ep[m] . us )  (256 threads)
// ---------------------------------------------------------------------------
__device__ __forceinline__ void logits_softmax(const float4* __restrict__ Ep,
                                               const float4* us,
                                               float* prob, float* red) {
    const int tid = threadIdx.x, w = tid >> 5, lane = tid & 31;
    const int q = lane & 3, sl = lane >> 2;
#pragma unroll
    for (int pass = 0; pass < 4; pass++) {
        const int m = pass * 64 + w * 8 + sl;
        float pd = 0.f;
#pragma unroll
        for (int j = 0; j < 8; j++) {
            float4 e  = Ep[(size_t)m * 32 + q + 4 * j];
            float4 uu = us[q + 4 * j];
            pd += e.x * uu.x + e.y * uu.y + e.z * uu.z + e.w * uu.w;
        }
        pd += __shfl_xor_sync(FULLMASK, pd, 1);
        pd += __shfl_xor_sync(FULLMASK, pd, 2);
        if (q == 0) prob[m] = pd;
    }
    __syncthreads();

    float x = prob[tid];
    float mx = x;
#pragma unroll
    for (int off = 16; off; off >>= 1)
        mx = fmaxf(mx, __shfl_xor_sync(FULLMASK, mx, off));
    if (lane == 0) red[w] = mx;
    __syncthreads();
    mx = red[0];
#pragma unroll
    for (int i = 1; i < 8; i++) mx = fmaxf(mx, red[i]);
    __syncthreads();

    float ev = __expf(x - mx);
    float sv = ev;
#pragma unroll
    for (int off = 16; off; off >>= 1)
        sv += __shfl_xor_sync(FULLMASK, sv, off);
    if (lane == 0) red[w] = sv;
    __syncthreads();
    float tot = red[0];
#pragma unroll
    for (int i = 1; i < 8; i++) tot += red[i];

    prob[tid] = ev / tot;
    __syncthreads();
}

// ---------------------------------------------------------------------------
// K1: gather t0 AND t1 in one launch (1024 blocks x 8 warps = 8192 units).
// No dependency between the two tables -> one drain boundary removed.
// ---------------------------------------------------------------------------
__global__ void __launch_bounds__(256) k1_kernel(const int* __restrict__ story,
                                                 const float* __restrict__ C) {
    const int w = blockIdx.x * 8 + (threadIdx.x >> 5);   // 0..8191
    const int t   = w >> 12;                             // 4096 units per table
    const int rem = w & 4095;
    gather_unit(story, C, t, rem / MEM, rem % MEM, threadIdx.x & 31);
}

// ---------------------------------------------------------------------------
// K2: blocks 0..15  : full hop chain for batch b:
//       u1 = mean_m E0[b][m]                     (hop0, uniform softmax)
//       prob1 = softmax(E0 . u1); u2 = u1 + sum prob1*E1; out[b] = u2
//       prob2 = softmax(E1 . u2) -> g_prob[b]
//     blocks 16..527: gather t2 (E2).
// The ~5us hop chain hides under the ~12us gather stream.
// ---------------------------------------------------------------------------
__global__ void __launch_bounds__(256) k2_kernel(const int* __restrict__ story,
                                                 const float* __restrict__ C,
                                                 float* __restrict__ out) {
    if (blockIdx.x >= 16) {
        const int w = (blockIdx.x - 16) * 8 + (threadIdx.x >> 5);
        gather_unit(story, C, 2, w / MEM, w % MEM, threadIdx.x & 31);
        return;
    }

    __shared__ float4 us[32];      // u1
    __shared__ float4 us2[32];     // u2
    __shared__ float  prob[MEM];
    __shared__ float4 wp[8][32];
    __shared__ float  red[8];

    const int b = blockIdx.x, tid = threadIdx.x, w = tid >> 5, lane = tid & 31;
    const float4* __restrict__ E0 = (const float4*)g_E[0][b];
    const float4* __restrict__ E1 = (const float4*)g_E[1][b];

    // ---- hop0: u1 = mean_m E0[b][m] (softmax of zero logits is uniform) ----
    {
        float4 acc = make_float4(0.f, 0.f, 0.f, 0.f);
#pragma unroll 4
        for (int k = 0; k < 32; k++) {
            float4 v = E0[(size_t)(w * 32 + k) * 32 + lane];
            acc.x += v.x; acc.y += v.y; acc.z += v.z; acc.w += v.w;
        }
        wp[w][lane] = acc;
        __syncthreads();
        if (tid < 32) {
            float4 a = wp[0][tid];
#pragma unroll
            for (int i = 1; i < 8; i++) {
                float4 c = wp[i][tid];
                a.x += c.x; a.y += c.y; a.z += c.z; a.w += c.w;
            }
            a.x *= (1.f / MEM); a.y *= (1.f / MEM);
            a.z *= (1.f / MEM); a.w *= (1.f / MEM);
            us[tid] = a;
        }
        __syncthreads();
    }

    // ---- hop1 attention: prob1 = softmax(E0 . u1) ----
    logits_softmax(E0, us, prob, red);

    // ---- o1 = sum_m prob1[m] * E1[b][m]; u2 = u1 + o1; out[b] = u2 ----
    {
        float4 acc = make_float4(0.f, 0.f, 0.f, 0.f);
#pragma unroll 4
        for (int k = 0; k < 32; k++) {
            const int mm = w * 32 + k;
            float p = prob[mm];
            float4 v = E1[(size_t)mm * 32 + lane];
            acc.x += p * v.x; acc.y += p * v.y; acc.z += p * v.z; acc.w += p * v.w;
        }
        wp[w][lane] = acc;
        __syncthreads();
        if (tid < 32) {
            float4 a = wp[0][tid];
#pragma unroll
            for (int i = 1; i < 8; i++) {
                float4 c = wp[i][tid];
                a.x += c.x; a.y += c.y; a.z += c.z; a.w += c.w;
            }
            float4 uu = us[tid];
            a.x += uu.x; a.y += uu.y; a.z += uu.z; a.w += uu.w;
            us2[tid] = a;
            ((float4*)out)[(size_t)b * 32 + tid] = a;   // K3 adds o2
        }
        __syncthreads();
    }

    // ---- logits2: prob2 = softmax(E1 . u2) -> g_prob[b] ----
    logits_softmax(E1, us2, prob, red);
    g_prob[b][tid] = prob[tid];
}

// ---------------------------------------------------------------------------
// K3: out[b] += sum_m prob2[m] * E2[b][m]; 8 blocks per batch (32 slots
// each) for a short high-MLP tail; atomicAdd merge (proven in R11).
// ---------------------------------------------------------------------------
__global__ void __launch_bounds__(256) k3_kernel(float* __restrict__ out) {
    __shared__ float4 wp[8][32];
    const int b = blockIdx.x >> 3, chunk = blockIdx.x & 7;
    const int tid = threadIdx.x, w = tid >> 5, lane = tid & 31;
    const float4* __restrict__ E2 = (const float4*)g_E[2][b];

    float4 acc = make_float4(0.f, 0.f, 0.f, 0.f);
#pragma unroll
    for (int k = 0; k < 4; k++) {
        const int m = chunk * 32 + w * 4 + k;
        float p = __ldg(&g_prob[b][m]);
        float4 v = E2[(size_t)m * 32 + lane];
        acc.x += p * v.x; acc.y += p * v.y; acc.z += p * v.z; acc.w += p * v.w;
    }
    wp[w][lane] = acc;
    __syncthreads();
    if (tid < 32) {
        float4 a = wp[0][tid];
#pragma unroll
        for (int i = 1; i < 8; i++) {
            float4 c = wp[i][tid];
            a.x += c.x; a.y += c.y; a.z += c.z; a.w += c.w;
        }
        float* dst = out + (size_t)b * EMB + tid * 4;
        atomicAdd(dst + 0, a.x); atomicAdd(dst + 1, a.y);
        atomicAdd(dst + 2, a.z); atomicAdd(dst + 3, a.w);
    }
}

extern "C" void kernel_launch(void* const* d_in, const int* in_sizes, int n_in,
                              void* d_out, int out_size) {
    const int*   story = (const int*)d_in[0];   // (256, 16, 64) int32
    const float* C     = (const float*)d_in[1]; // (4, 50257, 128) fp32
    float*       out   = (float*)d_out;         // (16, 128) fp32

    (void)in_sizes; (void)n_in; (void)out_size;

    k1_kernel<<<1024, 256>>>(story, C);         // gather t0 + t1
    k2_kernel<<<528, 256>>>(story, C, out);     // hop chain || gather t2
    k3_kernel<<<128, 256>>>(out);               // out += weighted-sum(E2)
}